// round 10
// baseline (speedup 1.0000x reference)
#include <cuda_runtime.h>
#include <cuda_fp16.h>
#include <cstdint>

typedef unsigned long long u64;
typedef unsigned int u32;

// ---------------- problem constants ----------------
#define MAXN 100000
#define MAXE 1000000
#define NB   16
#define EPT  9

// d_small layout (floats)
#define GPE  0
#define GPX  256
#define NAGG 512
#define EAGG 768
#define G1O  1024
#define GCO  1040
#define SMALLN 1056

// ---------------- device scratch ----------------
__device__ __align__(128) __half d_projS[(size_t)MAXN * 16];
__device__ __align__(128) __half d_projD[(size_t)MAXN * 16];
__device__ __align__(128) __half2 d_ec[(size_t)8 * MAXE];     // SoA: [h2][edge], relu'd e_new (step1)
__device__ __align__(128) __half2 d_aggE2[(size_t)MAXN * 8];  // fp16 scatter target
__device__ __align__(128) float d_xc[(size_t)MAXN * 16];
__device__ __align__(128) float d_counts[MAXN];
__device__ __align__(128) float d_small[SMALLN];
// PWL tables: 8 tables, each [j=0..7][seg=0..16] x {A_lo,A_hi,B_lo,B_hi}
__device__ __align__(128) float d_pwlAB[8 * 136 * 4];
__device__ __align__(128) float d_thr[2][16];   // 0 = E-encoder thresholds, 1 = X

// ---------------- helpers ----------------
__device__ __forceinline__ u64 pack2(float lo, float hi) {
    u64 r; asm("mov.b64 %0,{%1,%2};" : "=l"(r) : "f"(lo), "f"(hi)); return r;
}
__device__ __forceinline__ void unpack2(u64 v, float& lo, float& hi) {
    asm("mov.b64 {%0,%1},%2;" : "=f"(lo), "=f"(hi) : "l"(v));
}
__device__ __forceinline__ u64 fma2(u64 a, u64 b, u64 c) {
    u64 r; asm("fma.rn.f32x2 %0,%1,%2,%3;" : "=l"(r) : "l"(a), "l"(b), "l"(c)); return r;
}
__device__ __forceinline__ u64 add2(u64 a, u64 b) {
    u64 r; asm("add.rn.f32x2 %0,%1,%2;" : "=l"(r) : "l"(a), "l"(b)); return r;
}
__device__ __forceinline__ u64 h2f2(u32 u) {
    __half2 h = *reinterpret_cast<__half2*>(&u);
    float2 f = __half22float2(h);
    return pack2(f.x, f.y);
}
__device__ __forceinline__ u32 f2h2u(float a, float b) {
    __half2 h = __floats2half2_rn(a, b);
    return *reinterpret_cast<u32*>(&h);
}
__device__ __forceinline__ u32 hadd2u(u32 a, u32 b) {
    __half2 r = __hadd2(*reinterpret_cast<__half2*>(&a), *reinterpret_cast<__half2*>(&b));
    return *reinterpret_cast<u32*>(&r);
}

// Blackwell 256-bit global load/store (32B per lane in ONE instruction)
__device__ __forceinline__ void ldg256(const void* p, u32* r) {
    asm("ld.global.v8.b32 {%0,%1,%2,%3,%4,%5,%6,%7}, [%8];"
        : "=r"(r[0]), "=r"(r[1]), "=r"(r[2]), "=r"(r[3]),
          "=r"(r[4]), "=r"(r[5]), "=r"(r[6]), "=r"(r[7])
        : "l"(p));
}
__device__ __forceinline__ void stg256(void* p, const u32* r) {
    asm volatile("st.global.v8.b32 [%0], {%1,%2,%3,%4,%5,%6,%7,%8};"
                 :: "l"(p), "r"(r[0]), "r"(r[1]), "r"(r[2]), "r"(r[3]),
                    "r"(r[4]), "r"(r[5]), "r"(r[6]), "r"(r[7]) : "memory");
}

// acc2[8] += in[16] @ W2 (W2[k][j] packs columns 2j,2j+1 of row k)
__device__ __forceinline__ void mac16_2(const u64 (*__restrict__ W2)[8],
                                        const float* __restrict__ in,
                                        u64* __restrict__ acc2) {
#pragma unroll
    for (int k = 0; k < 16; k++) {
        u64 v2 = pack2(in[k], in[k]);
#pragma unroll
        for (int j = 0; j < 8; j++) acc2[j] = fma2(v2, W2[k][j], acc2[j]);
    }
}

#define RED4(p, a, b, c, d) \
    asm volatile("red.global.add.v4.f32 [%0], {%1,%2,%3,%4};" \
                 :: "l"(p), "f"(a), "f"(b), "f"(c), "f"(d) : "memory")
#define REDH8(p, a, b, c, d) \
    asm volatile("red.global.add.noftz.v4.f16x2 [%0], {%1,%2,%3,%4};" \
                 :: "l"(p), "r"(a), "r"(b), "r"(c), "r"(d) : "memory")

__device__ __forceinline__ void lane_flush16(int b, const float* v, float* gbase) {
    float* p = gbase + b * 16;
    RED4(p,      v[0],  v[1],  v[2],  v[3]);
    RED4(p + 4,  v[4],  v[5],  v[6],  v[7]);
    RED4(p + 8,  v[8],  v[9],  v[10], v[11]);
    RED4(p + 12, v[12], v[13], v[14], v[15]);
}

__device__ __forceinline__ void lane_flush16_h(int b, const u32* aggH, float* gbase) {
    float v[16];
#pragma unroll
    for (int j = 0; j < 8; j++) {
        float2 f = __half22float2(*reinterpret_cast<const __half2*>(&aggH[j]));
        v[2 * j] = f.x; v[2 * j + 1] = f.y;
    }
    lane_flush16(b, v, gbase);
}

__device__ __forceinline__ void warp_flush16(int curB, float* v, float* gbase) {
    const unsigned full = 0xffffffffu;
    int b0 = __shfl_sync(full, curB, 0);
    bool uni = __all_sync(full, (curB == b0) || (curB < 0));
    if (uni) {
#pragma unroll
        for (int h = 0; h < 16; h++) {
            float s = v[h];
            s += __shfl_xor_sync(full, s, 16);
            s += __shfl_xor_sync(full, s, 8);
            s += __shfl_xor_sync(full, s, 4);
            s += __shfl_xor_sync(full, s, 2);
            s += __shfl_xor_sync(full, s, 1);
            v[h] = s;
        }
        if (((threadIdx.x & 31) == 0) && b0 >= 0) lane_flush16(b0, v, gbase);
    } else if (curB >= 0) {
        lane_flush16(curB, v, gbase);
    }
}

__device__ __forceinline__ void warp_flush16_h(int curB, const u32* aggH, float* gbase) {
    float v[16];
#pragma unroll
    for (int j = 0; j < 8; j++) {
        float2 f = __half22float2(*reinterpret_cast<const __half2*>(&aggH[j]));
        v[2 * j] = f.x; v[2 * j + 1] = f.y;
    }
    warp_flush16(curB, v, gbase);
}

__device__ __forceinline__ int find_seg(float v, const float4* sThr4) {
    int seg = 0;
#pragma unroll
    for (int q = 0; q < 4; q++) {
        float4 T = sThr4[q];
        seg += (v > T.x) + (v > T.y) + (v > T.z) + (v > T.w);
    }
    return seg;
}

__device__ __forceinline__ void load_AB(float4* sdst, int tab, int t, int nthreads) {
    const float4* gsrc = reinterpret_cast<const float4*>(d_pwlAB) + tab * 136;
    for (int k = t; k < 136; k += nthreads) sdst[k] = gsrc[k];
}

// ---------------- PWL table builder ----------------
__global__ void build_pwl_kernel(
    const float* __restrict__ We_enc, const float* __restrict__ be_enc,
    const float* __restrict__ Wx_enc, const float* __restrict__ bx_enc,
    const float* __restrict__ We_core, const float* __restrict__ Wx_core) {
    __shared__ float sW[2][16], sB[2][16], sT[2][16];
    __shared__ int sAct[2][16], sRank[2][16];
    int t = threadIdx.x;
    const float INF = __int_as_float(0x7f800000);
    if (t < 32) {
        int set = t >> 4, h = t & 15;
        float w = set ? Wx_enc[h] : We_enc[h];
        float b = set ? bx_enc[h] : be_enc[h];
        float th; int actR;
        if (w > 0.f)      { th = -b / w; actR = 1; }
        else if (w < 0.f) { th = -b / w; actR = 0; }
        else if (b > 0.f) { th =  INF;   actR = 0; }
        else              { th = -INF;   actR = 0; }
        if (w == 0.f && b <= 0.f) { th = INF; actR = 1; }
        sW[set][h] = w; sB[set][h] = b; sT[set][h] = th; sAct[set][h] = actR;
        d_thr[set][h] = th;
    }
    __syncthreads();
    if (t < 32) {
        int set = t >> 4, h = t & 15;
        float th = sT[set][h];
        int r = 0;
        for (int k = 0; k < 16; k++) {
            float tk = sT[set][k];
            if (tk < th || (tk == th && k < h)) r++;
        }
        sRank[set][h] = r;
    }
    __syncthreads();
    for (int f = t; f < 8 * 136; f += blockDim.x) {
        int tab = f / 136;
        int j   = (f % 136) / 17;
        int seg = f % 17;
        int set = (tab < 2) ? 0 : 1;
        float a0 = 0.f, a1 = 0.f, b0 = 0.f, b1 = 0.f;
        for (int h = 0; h < 16; h++) {
            int active = sAct[set][h] ? (sRank[set][h] < seg) : (sRank[set][h] >= seg);
            if (!active) continue;
            int c0 = 2 * j, c1 = 2 * j + 1;
            float wc0, wc1;
            switch (tab) {
                case 0: wc0 = We_core[h*16+c0] + We_core[(16+h)*16+c0];
                        wc1 = We_core[h*16+c1] + We_core[(16+h)*16+c1]; break;
                case 1: wc0 = We_core[h*16+c0];        wc1 = We_core[h*16+c1];        break;
                case 2: wc0 = Wx_core[h*16+c0] + Wx_core[(16+h)*16+c0];
                        wc1 = Wx_core[h*16+c1] + Wx_core[(16+h)*16+c1]; break;
                case 3: wc0 = Wx_core[h*16+c0];        wc1 = Wx_core[h*16+c1];        break;
                case 4: wc0 = We_core[(32+h)*16+c0];   wc1 = We_core[(32+h)*16+c1];   break;
                case 5: wc0 = We_core[(64+h)*16+c0];   wc1 = We_core[(64+h)*16+c1];   break;
                case 6: wc0 = We_core[(32+h)*16+c0] + We_core[(48+h)*16+c0];
                        wc1 = We_core[(32+h)*16+c1] + We_core[(48+h)*16+c1]; break;
                default: wc0 = We_core[(64+h)*16+c0] + We_core[(80+h)*16+c0];
                         wc1 = We_core[(64+h)*16+c1] + We_core[(80+h)*16+c1]; break;
            }
            float w = sW[set][h], bb = sB[set][h];
            a0 = fmaf(w, wc0, a0);  a1 = fmaf(w, wc1, a1);
            b0 = fmaf(bb, wc0, b0); b1 = fmaf(bb, wc1, b1);
        }
        float* dst = d_pwlAB + (size_t)f * 4;
        dst[0] = a0; dst[1] = a1; dst[2] = b0; dst[3] = b1;
    }
}

// ---------------- setup kernels ----------------
__global__ void __launch_bounds__(256) setup_node_kernel(const float* __restrict__ x, int N) {
    __shared__ __align__(16) ulonglong2 sABS[136], sABD[136];
    __shared__ float4 sThr4[4];
    int t = threadIdx.x;
    load_AB(reinterpret_cast<float4*>(sABS), 6, t, 256);
    load_AB(reinterpret_cast<float4*>(sABD), 7, t, 256);
    if (t < 4) sThr4[t] = reinterpret_cast<const float4*>(d_thr[1])[t];
    __syncthreads();
    int n = blockIdx.x * 256 + t;
    if (n >= N) return;
    float xv = x[n];
    int seg = find_seg(xv, sThr4);
    u64 xv2 = pack2(xv, xv);
    u32 hs[8], hd[8];
#pragma unroll
    for (int j = 0; j < 8; j++) {
        ulonglong2 abS = sABS[j * 17 + seg];
        ulonglong2 abD = sABD[j * 17 + seg];
        float a, b;
        unpack2(fma2(xv2, abS.x, abS.y), a, b); hs[j] = f2h2u(a, b);
        unpack2(fma2(xv2, abD.x, abD.y), a, b); hd[j] = f2h2u(a, b);
    }
    stg256(d_projS + (size_t)n * 16, hs);
    stg256(d_projD + (size_t)n * 16, hd);
}

__global__ void setup_global_kernel(
    const float* __restrict__ g,
    const float* __restrict__ Wg_enc, const float* __restrict__ bg_enc,
    const float* __restrict__ We_core, const float* __restrict__ be_core,
    const float* __restrict__ Wx_core, const float* __restrict__ bx_core, int B) {
    int t = threadIdx.x;
    if (t < B) {
        float g1 = fmaxf(fmaf(g[t], Wg_enc[0], bg_enc[0]), 0.f);
        d_small[G1O + t] = g1;
        d_small[GCO + t] = g1;
    }
    __syncthreads();
    if (t < B * 16) {
        int b = t >> 4, h = t & 15;
        float g1 = d_small[G1O + b];
        d_small[GPE + t] = fmaf(g1, We_core[96 * 16 + h] + We_core[97 * 16 + h], be_core[h]);
        d_small[GPX + t] = fmaf(g1, Wx_core[48 * 16 + h] + Wx_core[49 * 16 + h], bx_core[h]);
    }
}

// ---------------- fused edge kernel (fp32 acc, fp16 eAgg, 3 CTAs/SM, 256-bit gathers) ----------------
template <int STEP>
__global__ void __launch_bounds__(256, 3) edge_kernel(
    const float* __restrict__ e,
    const int* __restrict__ src, const int* __restrict__ dst,
    const int* __restrict__ eidx,
    const float* __restrict__ We_core,
    const float* __restrict__ We_dec, const float* __restrict__ be_dec,
    const float* __restrict__ We_out, const float* __restrict__ be_out,
    float* __restrict__ out_e, int E) {
    __shared__ __align__(16) ulonglong2 sAB[136];      // PWL(e1 part)
    __shared__ __align__(16) u64 sWb2[16][8];          // ec weights (step2)
    __shared__ __align__(16) u64 sWdec2[16][8];
    __shared__ __align__(16) u64 sGproj2[NB][8];
    __shared__ u64 sBdec2[8];
    __shared__ float4 sThr4[4];
    __shared__ float sWoutT[2][16], sBout[2];

    int t = threadIdx.x;
    load_AB(reinterpret_cast<float4*>(sAB), (STEP == 1) ? 0 : 1, t, 256);
    if (t < 128) {
        int k = t >> 3, j = t & 7;
        if (STEP == 2)
            sWb2[k][j] = pack2(We_core[(16 + k) * 16 + 2 * j], We_core[(16 + k) * 16 + 2 * j + 1]);
        sWdec2[k][j] = pack2(We_dec[k * 16 + 2 * j], We_dec[k * 16 + 2 * j + 1]);
        sGproj2[k][j] = pack2(d_small[GPE + k * 16 + 2 * j], d_small[GPE + k * 16 + 2 * j + 1]);
    }
    if (t < 16) { sWoutT[0][t] = We_out[2 * t]; sWoutT[1][t] = We_out[2 * t + 1]; }
    if (t < 8) sBdec2[t] = pack2(be_dec[2 * t], be_dec[2 * t + 1]);
    if (t < 4) sThr4[t] = reinterpret_cast<const float4*>(d_thr[0])[t];
    if (t < 2) sBout[t] = be_out[t];
    __syncthreads();

    u32 eAggH[8];
#pragma unroll
    for (int j = 0; j < 8; j++) eAggH[j] = 0u;
    int curB = -1;

    int base = blockIdx.x * (256 * EPT);
#pragma unroll
    for (int it = 0; it < EPT; ++it) {
        int i = base + it * 256 + t;
        if (i < E) {
            float ev = e[i];
            int s = src[i], d = dst[i], b = eidx[i];

            // single 256-bit random gather per table
            u32 sw[8], dw[8];
            ldg256(d_projS + (size_t)s * 16, sw);
            ldg256(d_projD + (size_t)d * 16, dw);

            int seg = find_seg(ev, sThr4);
            u64 ev2 = pack2(ev, ev);

            u64 acc2[8];
#pragma unroll
            for (int j = 0; j < 8; j++) {
                ulonglong2 ab = sAB[j * 17 + seg];
                acc2[j] = add2(add2(h2f2(sw[j]), h2f2(dw[j])),
                               add2(sGproj2[b][j], fma2(ev2, ab.x, ab.y)));
            }
            if (STEP == 2) {
                // convert-as-you-go mac from fp16 SoA e_c
#pragma unroll
                for (int kk = 0; kk < 8; kk++) {
                    float2 f = __half22float2(d_ec[(size_t)kk * MAXE + i]);
                    u64 l2 = pack2(f.x, f.x), h2v = pack2(f.y, f.y);
#pragma unroll
                    for (int j = 0; j < 8; j++) acc2[j] = fma2(l2, sWb2[2 * kk][j], acc2[j]);
#pragma unroll
                    for (int j = 0; j < 8; j++) acc2[j] = fma2(h2v, sWb2[2 * kk + 1][j], acc2[j]);
                }
            }
            // relu in fp32; keep acc[16] for decoder, pack hh[8] for store/scatter/eAgg
            float acc[16];
            u32 hh[8];
#pragma unroll
            for (int j = 0; j < 8; j++) {
                float lo, hi; unpack2(acc2[j], lo, hi);
                lo = fmaxf(lo, 0.f); hi = fmaxf(hi, 0.f);
                acc[2 * j] = lo; acc[2 * j + 1] = hi;
                hh[j] = f2h2u(lo, hi);
            }

            if (STEP == 1) {
#pragma unroll
                for (int j = 0; j < 8; j++)
                    d_ec[(size_t)j * MAXE + i] = *reinterpret_cast<__half2*>(&hh[j]);
                asm volatile("red.global.add.f32 [%0], %1;"
                             :: "l"(d_counts + d), "f"(1.0f) : "memory");
            }
            // fp16 packed scatter-sum onto destination node
            {
                __half2* p = d_aggE2 + (size_t)d * 8;
                REDH8(p, hh[0], hh[1], hh[2], hh[3]);
                REDH8(p + 4, hh[4], hh[5], hh[6], hh[7]);
            }
            // per-graph edge aggregation (fp16 in-register)
            if (b != curB) {
                if (curB >= 0) lane_flush16_h(curB, eAggH, d_small + EAGG);
                curB = b;
#pragma unroll
                for (int j = 0; j < 8; j++) eAggH[j] = 0u;
            }
#pragma unroll
            for (int j = 0; j < 8; j++) eAggH[j] = hadd2u(eAggH[j], hh[j]);

            // decoder + output head (fp32 path)
            u64 dacc[8];
#pragma unroll
            for (int j = 0; j < 8; j++) dacc[j] = sBdec2[j];
            mac16_2(sWdec2, acc, dacc);
            float o0 = sBout[0], o1 = sBout[1];
#pragma unroll
            for (int j = 0; j < 8; j++) {
                float lo, hi; unpack2(dacc[j], lo, hi);
                float r0 = fmaxf(lo, 0.f), r1 = fmaxf(hi, 0.f);
                o0 = fmaf(r0, sWoutT[0][2 * j], fmaf(r1, sWoutT[0][2 * j + 1], o0));
                o1 = fmaf(r0, sWoutT[1][2 * j], fmaf(r1, sWoutT[1][2 * j + 1], o1));
            }
            reinterpret_cast<float2*>(out_e)[(size_t)(STEP - 1) * E + i] = make_float2(o0, o1);
        }
    }
    warp_flush16_h(curB, eAggH, d_small + EAGG);
}

// ---------------- node kernel ----------------
template <int STEP>
__global__ void __launch_bounds__(256) node_kernel(
    const float* __restrict__ x, const int* __restrict__ nidx,
    const float* __restrict__ Wx_core,
    const float* __restrict__ We_core,
    const float* __restrict__ Wx_dec, const float* __restrict__ bx_dec,
    const float* __restrict__ Wx_out, const float* __restrict__ bx_out,
    float* __restrict__ out_x, int N) {
    __shared__ __align__(16) ulonglong2 sABX[136];
    __shared__ __align__(16) ulonglong2 sABS[136], sABD[136]; // step1 only
    __shared__ __align__(16) u64 sWxB2[16][8];                // step2 only
    __shared__ __align__(16) u64 sWagg2[16][8], sWdec2[16][8];
    __shared__ __align__(16) u64 sWSb2[16][8], sWDb2[16][8];  // step1 only
    __shared__ __align__(16) u64 sGprojX2[NB][8];
    __shared__ u64 sBdec2[8];
    __shared__ float4 sThr4[4];
    __shared__ float sWoutT[2][16], sBout[2];

    int t = threadIdx.x;
    load_AB(reinterpret_cast<float4*>(sABX), (STEP == 1) ? 2 : 3, t, 256);
    if (STEP == 1) {
        load_AB(reinterpret_cast<float4*>(sABS), 4, t, 256);
        load_AB(reinterpret_cast<float4*>(sABD), 5, t, 256);
    }
    if (t < 128) {
        int k = t >> 3, j = t & 7;
        int c0 = 2 * j, c1 = 2 * j + 1;
        if (STEP == 1) {
            sWSb2[k][j] = pack2(We_core[(48 + k) * 16 + c0], We_core[(48 + k) * 16 + c1]);
            sWDb2[k][j] = pack2(We_core[(80 + k) * 16 + c0], We_core[(80 + k) * 16 + c1]);
        } else {
            sWxB2[k][j] = pack2(Wx_core[(16 + k) * 16 + c0], Wx_core[(16 + k) * 16 + c1]);
        }
        sWagg2[k][j] = pack2(Wx_core[(32 + k) * 16 + c0], Wx_core[(32 + k) * 16 + c1]);
        sWdec2[k][j] = pack2(Wx_dec[k * 16 + c0], Wx_dec[k * 16 + c1]);
        sGprojX2[k][j] = pack2(d_small[GPX + k * 16 + c0], d_small[GPX + k * 16 + c1]);
    }
    if (t < 16) { sWoutT[0][t] = Wx_out[2 * t]; sWoutT[1][t] = Wx_out[2 * t + 1]; }
    if (t < 8) sBdec2[t] = pack2(bx_dec[2 * t], bx_dec[2 * t + 1]);
    if (t < 4) sThr4[t] = reinterpret_cast<const float4*>(d_thr[1])[t];
    if (t < 2) sBout[t] = bx_out[t];
    __syncthreads();

    int n = blockIdx.x * 256 + t;
    float xnew[16];
#pragma unroll
    for (int hh = 0; hh < 16; hh++) xnew[hh] = 0.f;
    int b = -1;

    if (n < N) {
        b = nidx[n];
        float xv = x[n];
        int seg = find_seg(xv, sThr4);
        u64 xv2 = pack2(xv, xv);
        u64 acc2[8];
#pragma unroll
        for (int j = 0; j < 8; j++) {
            ulonglong2 ab = sABX[j * 17 + seg];
            acc2[j] = add2(sGprojX2[b][j], fma2(xv2, ab.x, ab.y));
        }
        if (STEP == 2) {
            float xc[16];
            u32 xr[8];
            ldg256(d_xc + (size_t)n * 16, xr);
#pragma unroll
            for (int q = 0; q < 8; q++) xc[q] = __uint_as_float(xr[q]);
            ldg256(d_xc + (size_t)n * 16 + 8, xr);
#pragma unroll
            for (int q = 0; q < 8; q++) xc[8 + q] = __uint_as_float(xr[q]);
            mac16_2(sWxB2, xc, acc2);
        }
        float inv = 1.0f / fmaxf(d_counts[n], 1.0f);
        float am[16];
        {
            u32 w[8];
            ldg256(d_aggE2 + (size_t)n * 8, w);
#pragma unroll
            for (int q = 0; q < 8; q++) {
                float2 f = __half22float2(*reinterpret_cast<__half2*>(&w[q]));
                am[2 * q] = f.x * inv; am[2 * q + 1] = f.y * inv;
            }
        }
        mac16_2(sWagg2, am, acc2);
#pragma unroll
        for (int j = 0; j < 8; j++) unpack2(acc2[j], xnew[2 * j], xnew[2 * j + 1]);
#pragma unroll
        for (int hh = 0; hh < 16; hh++) xnew[hh] = fmaxf(xnew[hh], 0.f);

        if (STEP == 1) {
            stg256(d_xc + (size_t)n * 16, reinterpret_cast<const u32*>(xnew));
            stg256(d_xc + (size_t)n * 16 + 8, reinterpret_cast<const u32*>(xnew) + 8);
            u64 psv2[8], pdv2[8];
#pragma unroll
            for (int j = 0; j < 8; j++) {
                ulonglong2 abS = sABS[j * 17 + seg];
                ulonglong2 abD = sABD[j * 17 + seg];
                psv2[j] = fma2(xv2, abS.x, abS.y);
                pdv2[j] = fma2(xv2, abD.x, abD.y);
            }
            mac16_2(sWSb2, xnew, psv2);
            mac16_2(sWDb2, xnew, pdv2);
            u32 hs[8], hd[8];
#pragma unroll
            for (int j = 0; j < 8; j++) {
                float a, c;
                unpack2(psv2[j], a, c); hs[j] = f2h2u(a, c);
                unpack2(pdv2[j], a, c); hd[j] = f2h2u(a, c);
            }
            stg256(d_projS + (size_t)n * 16, hs);
            stg256(d_projD + (size_t)n * 16, hd);
        }
        u64 xd2[8];
#pragma unroll
        for (int j = 0; j < 8; j++) xd2[j] = sBdec2[j];
        mac16_2(sWdec2, xnew, xd2);
        float o0 = sBout[0], o1 = sBout[1];
#pragma unroll
        for (int j = 0; j < 8; j++) {
            float lo, hi; unpack2(xd2[j], lo, hi);
            float r0 = fmaxf(lo, 0.f), r1 = fmaxf(hi, 0.f);
            o0 = fmaf(r0, sWoutT[0][2 * j], fmaf(r1, sWoutT[0][2 * j + 1], o0));
            o1 = fmaf(r0, sWoutT[1][2 * j], fmaf(r1, sWoutT[1][2 * j + 1], o1));
        }
        reinterpret_cast<float2*>(out_x)[(size_t)(STEP - 1) * N + n] = make_float2(o0, o1);
    }
    warp_flush16(b, xnew, d_small + NAGG);
}

// ---------------- global kernel ----------------
template <int STEP>
__global__ void global_kernel(
    const float* __restrict__ Wg_core, const float* __restrict__ bg_core,
    const float* __restrict__ Wg_dec, const float* __restrict__ bg_dec,
    const float* __restrict__ Wg_out, const float* __restrict__ bg_out,
    const float* __restrict__ We_core, const float* __restrict__ be_core,
    const float* __restrict__ Wx_core, const float* __restrict__ bx_core,
    float* __restrict__ out_g, int B) {
    int t = threadIdx.x;
    if (t < B) {
        float g1 = d_small[G1O + t], gc = d_small[GCO + t];
        float acc = bg_core[0] + g1 * Wg_core[0] + gc * Wg_core[1];
#pragma unroll
        for (int h = 0; h < 16; h++) acc = fmaf(d_small[NAGG + t * 16 + h], Wg_core[2 + h], acc);
#pragma unroll
        for (int h = 0; h < 16; h++) acc = fmaf(d_small[EAGG + t * 16 + h], Wg_core[18 + h], acc);
        float gn = fmaxf(acc, 0.f);
        d_small[GCO + t] = gn;
        float gd = fmaxf(fmaf(gn, Wg_dec[0], bg_dec[0]), 0.f);
        out_g[(STEP - 1) * B + t] = fmaf(gd, Wg_out[0], bg_out[0]);
    }
    __syncthreads();
    if (STEP == 1 && t < B * 16) {
        int b = t >> 4, h = t & 15;
        float g1 = d_small[G1O + b], gn = d_small[GCO + b];
        d_small[GPE + t] = fmaf(g1, We_core[96 * 16 + h], fmaf(gn, We_core[97 * 16 + h], be_core[h]));
        d_small[GPX + t] = fmaf(g1, Wx_core[48 * 16 + h], fmaf(gn, Wx_core[49 * 16 + h], bx_core[h]));
    }
}

// ---------------- launch ----------------
extern "C" void kernel_launch(void* const* d_in, const int* in_sizes, int n_in,
                              void* d_out, int out_size) {
    const float* x       = (const float*)d_in[0];
    const float* e       = (const float*)d_in[1];
    const float* g       = (const float*)d_in[2];
    const float* We_enc  = (const float*)d_in[3];
    const float* be_enc  = (const float*)d_in[4];
    const float* Wx_enc  = (const float*)d_in[5];
    const float* bx_enc  = (const float*)d_in[6];
    const float* Wg_enc  = (const float*)d_in[7];
    const float* bg_enc  = (const float*)d_in[8];
    const float* We_core = (const float*)d_in[9];
    const float* be_core = (const float*)d_in[10];
    const float* Wx_core = (const float*)d_in[11];
    const float* bx_core = (const float*)d_in[12];
    const float* Wg_core = (const float*)d_in[13];
    const float* bg_core = (const float*)d_in[14];
    const float* We_dec  = (const float*)d_in[15];
    const float* be_dec  = (const float*)d_in[16];
    const float* Wx_dec  = (const float*)d_in[17];
    const float* bx_dec  = (const float*)d_in[18];
    const float* Wg_dec  = (const float*)d_in[19];
    const float* bg_dec  = (const float*)d_in[20];
    const float* We_out  = (const float*)d_in[21];
    const float* be_out  = (const float*)d_in[22];
    const float* Wx_out  = (const float*)d_in[23];
    const float* bx_out  = (const float*)d_in[24];
    const float* Wg_out  = (const float*)d_in[25];
    const float* bg_out  = (const float*)d_in[26];
    const int*   edges   = (const int*)d_in[27];
    const int*   nidx    = (const int*)d_in[28];
    const int*   eidx    = (const int*)d_in[29];

    int N = in_sizes[0];
    int E = in_sizes[1];
    int B = in_sizes[2];
    float* out = (float*)d_out;
    float* out_e = out;
    float* out_x = out + (size_t)4 * E;
    float* out_g = out + (size_t)4 * E + (size_t)4 * N;

    const int* src = edges;
    const int* dst = edges + E;

    void *pCounts, *pAggE, *pSmall;
    cudaGetSymbolAddress(&pCounts, d_counts);
    cudaGetSymbolAddress(&pAggE, d_aggE2);
    cudaGetSymbolAddress(&pSmall, d_small);

    cudaMemsetAsync(pCounts, 0, (size_t)N * sizeof(float), 0);
    cudaMemsetAsync(pAggE, 0, (size_t)N * 8 * sizeof(__half2), 0);
    cudaMemsetAsync((char*)pSmall + NAGG * sizeof(float), 0, 512 * sizeof(float), 0);

    build_pwl_kernel<<<1, 256>>>(We_enc, be_enc, Wx_enc, bx_enc, We_core, Wx_core);
    setup_global_kernel<<<1, 256>>>(g, Wg_enc, bg_enc, We_core, be_core, Wx_core, bx_core, B);
    setup_node_kernel<<<(N + 255) / 256, 256>>>(x, N);

    int egrid = (E + 256 * EPT - 1) / (256 * EPT);
    int ngrid = (N + 255) / 256;

    // ---- step 1 ----
    edge_kernel<1><<<egrid, 256>>>(e, src, dst, eidx, We_core,
                                   We_dec, be_dec, We_out, be_out, out_e, E);
    node_kernel<1><<<ngrid, 256>>>(x, nidx, Wx_core, We_core,
                                   Wx_dec, bx_dec, Wx_out, bx_out, out_x, N);
    global_kernel<1><<<1, 256>>>(Wg_core, bg_core, Wg_dec, bg_dec, Wg_out, bg_out,
                                 We_core, be_core, Wx_core, bx_core, out_g, B);

    cudaMemsetAsync(pAggE, 0, (size_t)N * 8 * sizeof(__half2), 0);
    cudaMemsetAsync((char*)pSmall + NAGG * sizeof(float), 0, 512 * sizeof(float), 0);

    // ---- step 2 ----
    edge_kernel<2><<<egrid, 256>>>(e, src, dst, eidx, We_core,
                                   We_dec, be_dec, We_out, be_out, out_e, E);
    node_kernel<2><<<ngrid, 256>>>(x, nidx, Wx_core, We_core,
                                   Wx_dec, bx_dec, Wx_out, bx_out, out_x, N);
    global_kernel<2><<<1, 256>>>(Wg_core, bg_core, Wg_dec, bg_dec, Wg_out, bg_out,
                                 We_core, be_core, Wx_core, bx_core, out_g, B);
}

// round 11
// speedup vs baseline: 1.0769x; 1.0769x over previous
#include <cuda_runtime.h>
#include <cuda_fp16.h>
#include <cstdint>

typedef unsigned long long u64;
typedef unsigned int u32;

// ---------------- problem constants ----------------
#define MAXN 100000
#define MAXE 1000000
#define NB   16
#define EPT  9

// d_small layout (floats)
#define GPE  0
#define GPX  256
#define NAGG 512
#define EAGG 768
#define G1O  1024
#define GCO  1040
#define SMALLN 1056

// ---------------- device scratch (zero-initialized .bss; every launch restores zeros) ----------------
__device__ __align__(128) __half d_projS[(size_t)MAXN * 16];
__device__ __align__(128) __half d_projD[(size_t)MAXN * 16];
__device__ __align__(128) __half d_ecA[(size_t)MAXE * 16];    // AoS: 32B per edge, relu'd e_new
__device__ __align__(128) __half2 d_aggE2[(size_t)MAXN * 8];  // fp16 scatter target (self-zeroing)
__device__ __align__(128) float d_xc[(size_t)MAXN * 16];
__device__ __align__(128) float d_counts[MAXN];               // self-zeroing
__device__ __align__(128) float d_small[SMALLN];              // NAGG/EAGG self-zeroing
// PWL tables: 8 tables, each [j=0..7][seg=0..16] x {A_lo,A_hi,B_lo,B_hi}
__device__ __align__(128) float d_pwlAB[8 * 136 * 4];
__device__ __align__(128) float d_thr[2][16];   // 0 = E-encoder thresholds, 1 = X

// ---------------- helpers ----------------
__device__ __forceinline__ u64 pack2(float lo, float hi) {
    u64 r; asm("mov.b64 %0,{%1,%2};" : "=l"(r) : "f"(lo), "f"(hi)); return r;
}
__device__ __forceinline__ void unpack2(u64 v, float& lo, float& hi) {
    asm("mov.b64 {%0,%1},%2;" : "=f"(lo), "=f"(hi) : "l"(v));
}
__device__ __forceinline__ u64 fma2(u64 a, u64 b, u64 c) {
    u64 r; asm("fma.rn.f32x2 %0,%1,%2,%3;" : "=l"(r) : "l"(a), "l"(b), "l"(c)); return r;
}
__device__ __forceinline__ u64 add2(u64 a, u64 b) {
    u64 r; asm("add.rn.f32x2 %0,%1,%2;" : "=l"(r) : "l"(a), "l"(b)); return r;
}
__device__ __forceinline__ u64 h2f2(u32 u) {
    __half2 h = *reinterpret_cast<__half2*>(&u);
    float2 f = __half22float2(h);
    return pack2(f.x, f.y);
}
__device__ __forceinline__ u32 f2h2u(float a, float b) {
    __half2 h = __floats2half2_rn(a, b);
    return *reinterpret_cast<u32*>(&h);
}
__device__ __forceinline__ u32 hadd2u(u32 a, u32 b) {
    __half2 r = __hadd2(*reinterpret_cast<__half2*>(&a), *reinterpret_cast<__half2*>(&b));
    return *reinterpret_cast<u32*>(&r);
}

// Blackwell 256-bit global load/store (32B per lane in ONE instruction)
__device__ __forceinline__ void ldg256(const void* p, u32* r) {
    asm("ld.global.v8.b32 {%0,%1,%2,%3,%4,%5,%6,%7}, [%8];"
        : "=r"(r[0]), "=r"(r[1]), "=r"(r[2]), "=r"(r[3]),
          "=r"(r[4]), "=r"(r[5]), "=r"(r[6]), "=r"(r[7])
        : "l"(p));
}
__device__ __forceinline__ void stg256(void* p, const u32* r) {
    asm volatile("st.global.v8.b32 [%0], {%1,%2,%3,%4,%5,%6,%7,%8};"
                 :: "l"(p), "r"(r[0]), "r"(r[1]), "r"(r[2]), "r"(r[3]),
                    "r"(r[4]), "r"(r[5]), "r"(r[6]), "r"(r[7]) : "memory");
}

// acc2[8] += in[16] @ W2 (W2[k][j] packs columns 2j,2j+1 of row k)
__device__ __forceinline__ void mac16_2(const u64 (*__restrict__ W2)[8],
                                        const float* __restrict__ in,
                                        u64* __restrict__ acc2) {
#pragma unroll
    for (int k = 0; k < 16; k++) {
        u64 v2 = pack2(in[k], in[k]);
#pragma unroll
        for (int j = 0; j < 8; j++) acc2[j] = fma2(v2, W2[k][j], acc2[j]);
    }
}

#define RED4(p, a, b, c, d) \
    asm volatile("red.global.add.v4.f32 [%0], {%1,%2,%3,%4};" \
                 :: "l"(p), "f"(a), "f"(b), "f"(c), "f"(d) : "memory")
#define REDH8(p, a, b, c, d) \
    asm volatile("red.global.add.noftz.v4.f16x2 [%0], {%1,%2,%3,%4};" \
                 :: "l"(p), "r"(a), "r"(b), "r"(c), "r"(d) : "memory")

__device__ __forceinline__ void lane_flush16(int b, const float* v, float* gbase) {
    float* p = gbase + b * 16;
    RED4(p,      v[0],  v[1],  v[2],  v[3]);
    RED4(p + 4,  v[4],  v[5],  v[6],  v[7]);
    RED4(p + 8,  v[8],  v[9],  v[10], v[11]);
    RED4(p + 12, v[12], v[13], v[14], v[15]);
}

__device__ __forceinline__ void lane_flush16_h(int b, const u32* aggH, float* gbase) {
    float v[16];
#pragma unroll
    for (int j = 0; j < 8; j++) {
        float2 f = __half22float2(*reinterpret_cast<const __half2*>(&aggH[j]));
        v[2 * j] = f.x; v[2 * j + 1] = f.y;
    }
    lane_flush16(b, v, gbase);
}

__device__ __forceinline__ void warp_flush16(int curB, float* v, float* gbase) {
    const unsigned full = 0xffffffffu;
    int b0 = __shfl_sync(full, curB, 0);
    bool uni = __all_sync(full, (curB == b0) || (curB < 0));
    if (uni) {
#pragma unroll
        for (int h = 0; h < 16; h++) {
            float s = v[h];
            s += __shfl_xor_sync(full, s, 16);
            s += __shfl_xor_sync(full, s, 8);
            s += __shfl_xor_sync(full, s, 4);
            s += __shfl_xor_sync(full, s, 2);
            s += __shfl_xor_sync(full, s, 1);
            v[h] = s;
        }
        if (((threadIdx.x & 31) == 0) && b0 >= 0) lane_flush16(b0, v, gbase);
    } else if (curB >= 0) {
        lane_flush16(curB, v, gbase);
    }
}

__device__ __forceinline__ void warp_flush16_h(int curB, const u32* aggH, float* gbase) {
    float v[16];
#pragma unroll
    for (int j = 0; j < 8; j++) {
        float2 f = __half22float2(*reinterpret_cast<const __half2*>(&aggH[j]));
        v[2 * j] = f.x; v[2 * j + 1] = f.y;
    }
    warp_flush16(curB, v, gbase);
}

__device__ __forceinline__ int find_seg(float v, const float4* sThr4) {
    int seg = 0;
#pragma unroll
    for (int q = 0; q < 4; q++) {
        float4 T = sThr4[q];
        seg += (v > T.x) + (v > T.y) + (v > T.z) + (v > T.w);
    }
    return seg;
}

__device__ __forceinline__ void load_AB(float4* sdst, int tab, int t, int nthreads) {
    const float4* gsrc = reinterpret_cast<const float4*>(d_pwlAB) + tab * 136;
    for (int k = t; k < 136; k += nthreads) sdst[k] = gsrc[k];
}

// ---------------- fused setup: block 0 = PWL tables, block 1 = global encoder ----------------
__global__ void setup_small_kernel(
    const float* __restrict__ We_enc, const float* __restrict__ be_enc,
    const float* __restrict__ Wx_enc, const float* __restrict__ bx_enc,
    const float* __restrict__ We_core, const float* __restrict__ Wx_core,
    const float* __restrict__ g,
    const float* __restrict__ Wg_enc, const float* __restrict__ bg_enc,
    const float* __restrict__ be_core, const float* __restrict__ bx_core, int B) {
    int t = threadIdx.x;
    if (blockIdx.x == 1) {
        // ---- setup_global ----
        __shared__ float sG1[NB];
        if (t < B) {
            float g1 = fmaxf(fmaf(g[t], Wg_enc[0], bg_enc[0]), 0.f);
            sG1[t] = g1;
            d_small[G1O + t] = g1;
            d_small[GCO + t] = g1;
        }
        __syncthreads();
        if (t < B * 16) {
            int b = t >> 4, h = t & 15;
            float g1 = sG1[b];
            d_small[GPE + t] = fmaf(g1, We_core[96 * 16 + h] + We_core[97 * 16 + h], be_core[h]);
            d_small[GPX + t] = fmaf(g1, Wx_core[48 * 16 + h] + Wx_core[49 * 16 + h], bx_core[h]);
        }
        return;
    }
    // ---- build_pwl ----
    __shared__ float sW[2][16], sB[2][16], sT[2][16];
    __shared__ int sAct[2][16], sRank[2][16];
    const float INF = __int_as_float(0x7f800000);
    if (t < 32) {
        int set = t >> 4, h = t & 15;
        float w = set ? Wx_enc[h] : We_enc[h];
        float b = set ? bx_enc[h] : be_enc[h];
        float th; int actR;
        if (w > 0.f)      { th = -b / w; actR = 1; }
        else if (w < 0.f) { th = -b / w; actR = 0; }
        else if (b > 0.f) { th =  INF;   actR = 0; }
        else              { th = -INF;   actR = 0; }
        if (w == 0.f && b <= 0.f) { th = INF; actR = 1; }
        sW[set][h] = w; sB[set][h] = b; sT[set][h] = th; sAct[set][h] = actR;
        d_thr[set][h] = th;
    }
    __syncthreads();
    if (t < 32) {
        int set = t >> 4, h = t & 15;
        float th = sT[set][h];
        int r = 0;
        for (int k = 0; k < 16; k++) {
            float tk = sT[set][k];
            if (tk < th || (tk == th && k < h)) r++;
        }
        sRank[set][h] = r;
    }
    __syncthreads();
    for (int f = t; f < 8 * 136; f += blockDim.x) {
        int tab = f / 136;
        int j   = (f % 136) / 17;
        int seg = f % 17;
        int set = (tab < 2) ? 0 : 1;
        float a0 = 0.f, a1 = 0.f, b0 = 0.f, b1 = 0.f;
        for (int h = 0; h < 16; h++) {
            int active = sAct[set][h] ? (sRank[set][h] < seg) : (sRank[set][h] >= seg);
            if (!active) continue;
            int c0 = 2 * j, c1 = 2 * j + 1;
            float wc0, wc1;
            switch (tab) {
                case 0: wc0 = We_core[h*16+c0] + We_core[(16+h)*16+c0];
                        wc1 = We_core[h*16+c1] + We_core[(16+h)*16+c1]; break;
                case 1: wc0 = We_core[h*16+c0];        wc1 = We_core[h*16+c1];        break;
                case 2: wc0 = Wx_core[h*16+c0] + Wx_core[(16+h)*16+c0];
                        wc1 = Wx_core[h*16+c1] + Wx_core[(16+h)*16+c1]; break;
                case 3: wc0 = Wx_core[h*16+c0];        wc1 = Wx_core[h*16+c1];        break;
                case 4: wc0 = We_core[(32+h)*16+c0];   wc1 = We_core[(32+h)*16+c1];   break;
                case 5: wc0 = We_core[(64+h)*16+c0];   wc1 = We_core[(64+h)*16+c1];   break;
                case 6: wc0 = We_core[(32+h)*16+c0] + We_core[(48+h)*16+c0];
                        wc1 = We_core[(32+h)*16+c1] + We_core[(48+h)*16+c1]; break;
                default: wc0 = We_core[(64+h)*16+c0] + We_core[(80+h)*16+c0];
                         wc1 = We_core[(64+h)*16+c1] + We_core[(80+h)*16+c1]; break;
            }
            float w = sW[set][h], bb = sB[set][h];
            a0 = fmaf(w, wc0, a0);  a1 = fmaf(w, wc1, a1);
            b0 = fmaf(bb, wc0, b0); b1 = fmaf(bb, wc1, b1);
        }
        float* dst = d_pwlAB + (size_t)f * 4;
        dst[0] = a0; dst[1] = a1; dst[2] = b0; dst[3] = b1;
    }
}

// ---------------- setup_node ----------------
__global__ void __launch_bounds__(256) setup_node_kernel(const float* __restrict__ x, int N) {
    __shared__ __align__(16) ulonglong2 sABS[136], sABD[136];
    __shared__ float4 sThr4[4];
    int t = threadIdx.x;
    load_AB(reinterpret_cast<float4*>(sABS), 6, t, 256);
    load_AB(reinterpret_cast<float4*>(sABD), 7, t, 256);
    if (t < 4) sThr4[t] = reinterpret_cast<const float4*>(d_thr[1])[t];
    __syncthreads();
    int n = blockIdx.x * 256 + t;
    if (n >= N) return;
    float xv = x[n];
    int seg = find_seg(xv, sThr4);
    u64 xv2 = pack2(xv, xv);
    u32 hs[8], hd[8];
#pragma unroll
    for (int j = 0; j < 8; j++) {
        ulonglong2 abS = sABS[j * 17 + seg];
        ulonglong2 abD = sABD[j * 17 + seg];
        float a, b;
        unpack2(fma2(xv2, abS.x, abS.y), a, b); hs[j] = f2h2u(a, b);
        unpack2(fma2(xv2, abD.x, abD.y), a, b); hd[j] = f2h2u(a, b);
    }
    stg256(d_projS + (size_t)n * 16, hs);
    stg256(d_projD + (size_t)n * 16, hd);
}

// ---------------- fused edge kernel (fp32 acc, fp16 eAgg, 3 CTAs/SM) ----------------
template <int STEP>
__global__ void __launch_bounds__(256, 3) edge_kernel(
    const float* __restrict__ e,
    const int* __restrict__ src, const int* __restrict__ dst,
    const int* __restrict__ eidx,
    const float* __restrict__ We_core,
    const float* __restrict__ We_dec, const float* __restrict__ be_dec,
    const float* __restrict__ We_out, const float* __restrict__ be_out,
    float* __restrict__ out_e, int E) {
    __shared__ __align__(16) ulonglong2 sAB[136];      // PWL(e1 part)
    __shared__ __align__(16) u64 sWb2[16][8];          // ec weights (step2)
    __shared__ __align__(16) u64 sWdec2[16][8];
    __shared__ __align__(16) u64 sGproj2[NB][8];
    __shared__ u64 sBdec2[8];
    __shared__ float4 sThr4[4];
    __shared__ float sWoutT[2][16], sBout[2];

    int t = threadIdx.x;
    load_AB(reinterpret_cast<float4*>(sAB), (STEP == 1) ? 0 : 1, t, 256);
    if (t < 128) {
        int k = t >> 3, j = t & 7;
        if (STEP == 2)
            sWb2[k][j] = pack2(We_core[(16 + k) * 16 + 2 * j], We_core[(16 + k) * 16 + 2 * j + 1]);
        sWdec2[k][j] = pack2(We_dec[k * 16 + 2 * j], We_dec[k * 16 + 2 * j + 1]);
        sGproj2[k][j] = pack2(d_small[GPE + k * 16 + 2 * j], d_small[GPE + k * 16 + 2 * j + 1]);
    }
    if (t < 16) { sWoutT[0][t] = We_out[2 * t]; sWoutT[1][t] = We_out[2 * t + 1]; }
    if (t < 8) sBdec2[t] = pack2(be_dec[2 * t], be_dec[2 * t + 1]);
    if (t < 4) sThr4[t] = reinterpret_cast<const float4*>(d_thr[0])[t];
    if (t < 2) sBout[t] = be_out[t];
    __syncthreads();

    u32 eAggH[8];
#pragma unroll
    for (int j = 0; j < 8; j++) eAggH[j] = 0u;
    int curB = -1;

    int base = blockIdx.x * (256 * EPT);
#pragma unroll
    for (int it = 0; it < EPT; ++it) {
        int i = base + it * 256 + t;
        if (i < E) {
            float ev = e[i];
            int s = src[i], d = dst[i], b = eidx[i];

            u32 sw[8], dw[8];
            ldg256(d_projS + (size_t)s * 16, sw);
            ldg256(d_projD + (size_t)d * 16, dw);

            int seg = find_seg(ev, sThr4);
            u64 ev2 = pack2(ev, ev);

            u64 acc2[8];
#pragma unroll
            for (int j = 0; j < 8; j++) {
                ulonglong2 ab = sAB[j * 17 + seg];
                acc2[j] = add2(add2(h2f2(sw[j]), h2f2(dw[j])),
                               add2(sGproj2[b][j], fma2(ev2, ab.x, ab.y)));
            }
            if (STEP == 2) {
                // convert-as-you-go mac from fp16 AoS e_c (one 256-bit load)
                u32 ec[8];
                ldg256(d_ecA + (size_t)i * 16, ec);
#pragma unroll
                for (int kk = 0; kk < 8; kk++) {
                    float lo, hi; unpack2(h2f2(ec[kk]), lo, hi);
                    u64 l2 = pack2(lo, lo), h2v = pack2(hi, hi);
#pragma unroll
                    for (int j = 0; j < 8; j++) acc2[j] = fma2(l2, sWb2[2 * kk][j], acc2[j]);
#pragma unroll
                    for (int j = 0; j < 8; j++) acc2[j] = fma2(h2v, sWb2[2 * kk + 1][j], acc2[j]);
                }
            }
            // relu in fp32; keep acc[16] for decoder, pack hh[8] for store/scatter/eAgg
            float acc[16];
            u32 hh[8];
#pragma unroll
            for (int j = 0; j < 8; j++) {
                float lo, hi; unpack2(acc2[j], lo, hi);
                lo = fmaxf(lo, 0.f); hi = fmaxf(hi, 0.f);
                acc[2 * j] = lo; acc[2 * j + 1] = hi;
                hh[j] = f2h2u(lo, hi);
            }

            if (STEP == 1) {
                stg256(d_ecA + (size_t)i * 16, hh);
                asm volatile("red.global.add.f32 [%0], %1;"
                             :: "l"(d_counts + d), "f"(1.0f) : "memory");
            }
            // fp16 packed scatter-sum onto destination node
            {
                __half2* p = d_aggE2 + (size_t)d * 8;
                REDH8(p, hh[0], hh[1], hh[2], hh[3]);
                REDH8(p + 4, hh[4], hh[5], hh[6], hh[7]);
            }
            // per-graph edge aggregation (fp16 in-register)
            if (b != curB) {
                if (curB >= 0) lane_flush16_h(curB, eAggH, d_small + EAGG);
                curB = b;
#pragma unroll
                for (int j = 0; j < 8; j++) eAggH[j] = 0u;
            }
#pragma unroll
            for (int j = 0; j < 8; j++) eAggH[j] = hadd2u(eAggH[j], hh[j]);

            // decoder + output head (fp32 path)
            u64 dacc[8];
#pragma unroll
            for (int j = 0; j < 8; j++) dacc[j] = sBdec2[j];
            mac16_2(sWdec2, acc, dacc);
            float o0 = sBout[0], o1 = sBout[1];
#pragma unroll
            for (int j = 0; j < 8; j++) {
                float lo, hi; unpack2(dacc[j], lo, hi);
                float r0 = fmaxf(lo, 0.f), r1 = fmaxf(hi, 0.f);
                o0 = fmaf(r0, sWoutT[0][2 * j], fmaf(r1, sWoutT[0][2 * j + 1], o0));
                o1 = fmaf(r0, sWoutT[1][2 * j], fmaf(r1, sWoutT[1][2 * j + 1], o1));
            }
            reinterpret_cast<float2*>(out_e)[(size_t)(STEP - 1) * E + i] = make_float2(o0, o1);
        }
    }
    warp_flush16_h(curB, eAggH, d_small + EAGG);
}

// ---------------- node kernel (self-zeroes aggE2; counts in step2) ----------------
template <int STEP>
__global__ void __launch_bounds__(256) node_kernel(
    const float* __restrict__ x, const int* __restrict__ nidx,
    const float* __restrict__ Wx_core,
    const float* __restrict__ We_core,
    const float* __restrict__ Wx_dec, const float* __restrict__ bx_dec,
    const float* __restrict__ Wx_out, const float* __restrict__ bx_out,
    float* __restrict__ out_x, int N) {
    __shared__ __align__(16) ulonglong2 sABX[136];
    __shared__ __align__(16) ulonglong2 sABS[136], sABD[136]; // step1 only
    __shared__ __align__(16) u64 sWxB2[16][8];                // step2 only
    __shared__ __align__(16) u64 sWagg2[16][8], sWdec2[16][8];
    __shared__ __align__(16) u64 sWSb2[16][8], sWDb2[16][8];  // step1 only
    __shared__ __align__(16) u64 sGprojX2[NB][8];
    __shared__ u64 sBdec2[8];
    __shared__ float4 sThr4[4];
    __shared__ float sWoutT[2][16], sBout[2];

    int t = threadIdx.x;
    load_AB(reinterpret_cast<float4*>(sABX), (STEP == 1) ? 2 : 3, t, 256);
    if (STEP == 1) {
        load_AB(reinterpret_cast<float4*>(sABS), 4, t, 256);
        load_AB(reinterpret_cast<float4*>(sABD), 5, t, 256);
    }
    if (t < 128) {
        int k = t >> 3, j = t & 7;
        int c0 = 2 * j, c1 = 2 * j + 1;
        if (STEP == 1) {
            sWSb2[k][j] = pack2(We_core[(48 + k) * 16 + c0], We_core[(48 + k) * 16 + c1]);
            sWDb2[k][j] = pack2(We_core[(80 + k) * 16 + c0], We_core[(80 + k) * 16 + c1]);
        } else {
            sWxB2[k][j] = pack2(Wx_core[(16 + k) * 16 + c0], Wx_core[(16 + k) * 16 + c1]);
        }
        sWagg2[k][j] = pack2(Wx_core[(32 + k) * 16 + c0], Wx_core[(32 + k) * 16 + c1]);
        sWdec2[k][j] = pack2(Wx_dec[k * 16 + c0], Wx_dec[k * 16 + c1]);
        sGprojX2[k][j] = pack2(d_small[GPX + k * 16 + c0], d_small[GPX + k * 16 + c1]);
    }
    if (t < 16) { sWoutT[0][t] = Wx_out[2 * t]; sWoutT[1][t] = Wx_out[2 * t + 1]; }
    if (t < 8) sBdec2[t] = pack2(bx_dec[2 * t], bx_dec[2 * t + 1]);
    if (t < 4) sThr4[t] = reinterpret_cast<const float4*>(d_thr[1])[t];
    if (t < 2) sBout[t] = bx_out[t];
    __syncthreads();

    int n = blockIdx.x * 256 + t;
    float xnew[16];
#pragma unroll
    for (int hh = 0; hh < 16; hh++) xnew[hh] = 0.f;
    int b = -1;

    if (n < N) {
        b = nidx[n];
        float xv = x[n];
        int seg = find_seg(xv, sThr4);
        u64 xv2 = pack2(xv, xv);
        u64 acc2[8];
#pragma unroll
        for (int j = 0; j < 8; j++) {
            ulonglong2 ab = sABX[j * 17 + seg];
            acc2[j] = add2(sGprojX2[b][j], fma2(xv2, ab.x, ab.y));
        }
        if (STEP == 2) {
            float xc[16];
            u32 xr[8];
            ldg256(d_xc + (size_t)n * 16, xr);
#pragma unroll
            for (int q = 0; q < 8; q++) xc[q] = __uint_as_float(xr[q]);
            ldg256(d_xc + (size_t)n * 16 + 8, xr);
#pragma unroll
            for (int q = 0; q < 8; q++) xc[8 + q] = __uint_as_float(xr[q]);
            mac16_2(sWxB2, xc, acc2);
        }
        float cnt = d_counts[n];
        float inv = 1.0f / fmaxf(cnt, 1.0f);
        float am[16];
        {
            u32 w[8];
            ldg256(d_aggE2 + (size_t)n * 8, w);
#pragma unroll
            for (int q = 0; q < 8; q++) {
                float2 f = __half22float2(*reinterpret_cast<__half2*>(&w[q]));
                am[2 * q] = f.x * inv; am[2 * q + 1] = f.y * inv;
            }
        }
        // self-zero the scatter buffers for the next consumer/replay
        {
            u32 z[8] = {0, 0, 0, 0, 0, 0, 0, 0};
            stg256(d_aggE2 + (size_t)n * 8, z);
            if (STEP == 2) d_counts[n] = 0.f;
        }
        mac16_2(sWagg2, am, acc2);
#pragma unroll
        for (int j = 0; j < 8; j++) unpack2(acc2[j], xnew[2 * j], xnew[2 * j + 1]);
#pragma unroll
        for (int hh = 0; hh < 16; hh++) xnew[hh] = fmaxf(xnew[hh], 0.f);

        if (STEP == 1) {
            stg256(d_xc + (size_t)n * 16, reinterpret_cast<const u32*>(xnew));
            stg256(d_xc + (size_t)n * 16 + 8, reinterpret_cast<const u32*>(xnew) + 8);
            u64 psv2[8], pdv2[8];
#pragma unroll
            for (int j = 0; j < 8; j++) {
                ulonglong2 abS = sABS[j * 17 + seg];
                ulonglong2 abD = sABD[j * 17 + seg];
                psv2[j] = fma2(xv2, abS.x, abS.y);
                pdv2[j] = fma2(xv2, abD.x, abD.y);
            }
            mac16_2(sWSb2, xnew, psv2);
            mac16_2(sWDb2, xnew, pdv2);
            u32 hs[8], hd[8];
#pragma unroll
            for (int j = 0; j < 8; j++) {
                float a, c;
                unpack2(psv2[j], a, c); hs[j] = f2h2u(a, c);
                unpack2(pdv2[j], a, c); hd[j] = f2h2u(a, c);
            }
            stg256(d_projS + (size_t)n * 16, hs);
            stg256(d_projD + (size_t)n * 16, hd);
        }
        u64 xd2[8];
#pragma unroll
        for (int j = 0; j < 8; j++) xd2[j] = sBdec2[j];
        mac16_2(sWdec2, xnew, xd2);
        float o0 = sBout[0], o1 = sBout[1];
#pragma unroll
        for (int j = 0; j < 8; j++) {
            float lo, hi; unpack2(xd2[j], lo, hi);
            float r0 = fmaxf(lo, 0.f), r1 = fmaxf(hi, 0.f);
            o0 = fmaf(r0, sWoutT[0][2 * j], fmaf(r1, sWoutT[0][2 * j + 1], o0));
            o1 = fmaf(r0, sWoutT[1][2 * j], fmaf(r1, sWoutT[1][2 * j + 1], o1));
        }
        reinterpret_cast<float2*>(out_x)[(size_t)(STEP - 1) * N + n] = make_float2(o0, o1);
    }
    warp_flush16(b, xnew, d_small + NAGG);
}

// ---------------- global kernel (self-zeroes NAGG/EAGG) ----------------
template <int STEP>
__global__ void global_kernel(
    const float* __restrict__ Wg_core, const float* __restrict__ bg_core,
    const float* __restrict__ Wg_dec, const float* __restrict__ bg_dec,
    const float* __restrict__ Wg_out, const float* __restrict__ bg_out,
    const float* __restrict__ We_core, const float* __restrict__ be_core,
    const float* __restrict__ Wx_core, const float* __restrict__ bx_core,
    float* __restrict__ out_g, int B) {
    int t = threadIdx.x;
    if (t < B) {
        float g1 = d_small[G1O + t], gc = d_small[GCO + t];
        float acc = bg_core[0] + g1 * Wg_core[0] + gc * Wg_core[1];
#pragma unroll
        for (int h = 0; h < 16; h++) acc = fmaf(d_small[NAGG + t * 16 + h], Wg_core[2 + h], acc);
#pragma unroll
        for (int h = 0; h < 16; h++) acc = fmaf(d_small[EAGG + t * 16 + h], Wg_core[18 + h], acc);
        float gn = fmaxf(acc, 0.f);
        d_small[GCO + t] = gn;
        float gd = fmaxf(fmaf(gn, Wg_dec[0], bg_dec[0]), 0.f);
        out_g[(STEP - 1) * B + t] = fmaf(gd, Wg_out[0], bg_out[0]);
    }
    __syncthreads();
    // zero NAGG/EAGG for the next step / next replay
    d_small[NAGG + t] = 0.f;
    d_small[EAGG + t] = 0.f;
    if (STEP == 1 && t < B * 16) {
        int b = t >> 4, h = t & 15;
        float g1 = d_small[G1O + b], gn = d_small[GCO + b];
        d_small[GPE + t] = fmaf(g1, We_core[96 * 16 + h], fmaf(gn, We_core[97 * 16 + h], be_core[h]));
        d_small[GPX + t] = fmaf(g1, Wx_core[48 * 16 + h], fmaf(gn, Wx_core[49 * 16 + h], bx_core[h]));
    }
}

// ---------------- launch (8 graph nodes, no memsets) ----------------
extern "C" void kernel_launch(void* const* d_in, const int* in_sizes, int n_in,
                              void* d_out, int out_size) {
    const float* x       = (const float*)d_in[0];
    const float* e       = (const float*)d_in[1];
    const float* g       = (const float*)d_in[2];
    const float* We_enc  = (const float*)d_in[3];
    const float* be_enc  = (const float*)d_in[4];
    const float* Wx_enc  = (const float*)d_in[5];
    const float* bx_enc  = (const float*)d_in[6];
    const float* Wg_enc  = (const float*)d_in[7];
    const float* bg_enc  = (const float*)d_in[8];
    const float* We_core = (const float*)d_in[9];
    const float* be_core = (const float*)d_in[10];
    const float* Wx_core = (const float*)d_in[11];
    const float* bx_core = (const float*)d_in[12];
    const float* Wg_core = (const float*)d_in[13];
    const float* bg_core = (const float*)d_in[14];
    const float* We_dec  = (const float*)d_in[15];
    const float* be_dec  = (const float*)d_in[16];
    const float* Wx_dec  = (const float*)d_in[17];
    const float* bx_dec  = (const float*)d_in[18];
    const float* Wg_dec  = (const float*)d_in[19];
    const float* bg_dec  = (const float*)d_in[20];
    const float* We_out  = (const float*)d_in[21];
    const float* be_out  = (const float*)d_in[22];
    const float* Wx_out  = (const float*)d_in[23];
    const float* bx_out  = (const float*)d_in[24];
    const float* Wg_out  = (const float*)d_in[25];
    const float* bg_out  = (const float*)d_in[26];
    const int*   edges   = (const int*)d_in[27];
    const int*   nidx    = (const int*)d_in[28];
    const int*   eidx    = (const int*)d_in[29];

    int N = in_sizes[0];
    int E = in_sizes[1];
    int B = in_sizes[2];
    float* out = (float*)d_out;
    float* out_e = out;
    float* out_x = out + (size_t)4 * E;
    float* out_g = out + (size_t)4 * E + (size_t)4 * N;

    const int* src = edges;
    const int* dst = edges + E;

    setup_small_kernel<<<2, 256>>>(We_enc, be_enc, Wx_enc, bx_enc, We_core, Wx_core,
                                   g, Wg_enc, bg_enc, be_core, bx_core, B);
    setup_node_kernel<<<(N + 255) / 256, 256>>>(x, N);

    int egrid = (E + 256 * EPT - 1) / (256 * EPT);
    int ngrid = (N + 255) / 256;

    // ---- step 1 ----
    edge_kernel<1><<<egrid, 256>>>(e, src, dst, eidx, We_core,
                                   We_dec, be_dec, We_out, be_out, out_e, E);
    node_kernel<1><<<ngrid, 256>>>(x, nidx, Wx_core, We_core,
                                   Wx_dec, bx_dec, Wx_out, bx_out, out_x, N);
    global_kernel<1><<<1, 256>>>(Wg_core, bg_core, Wg_dec, bg_dec, Wg_out, bg_out,
                                 We_core, be_core, Wx_core, bx_core, out_g, B);

    // ---- step 2 ----
    edge_kernel<2><<<egrid, 256>>>(e, src, dst, eidx, We_core,
                                   We_dec, be_dec, We_out, be_out, out_e, E);
    node_kernel<2><<<ngrid, 256>>>(x, nidx, Wx_core, We_core,
                                   Wx_dec, bx_dec, Wx_out, bx_out, out_x, N);
    global_kernel<2><<<1, 256>>>(Wg_core, bg_core, Wg_dec, bg_dec, Wg_out, bg_out,
                                 We_core, be_core, Wx_core, bx_core, out_g, B);
}

// round 13
// speedup vs baseline: 1.1646x; 1.0814x over previous
#include <cuda_runtime.h>
#include <cuda_fp16.h>
#include <cstdint>

typedef unsigned long long u64;
typedef unsigned int u32;

// ---------------- problem constants ----------------
#define MAXN 100000
#define MAXE 1000000
#define NB   16
#define EPT  9

// d_small layout (floats)
#define GPE  0
#define GPX  256
#define NAGG 512
#define EAGG 768
#define G1O  1024
#define GCO  1040
#define SMALLN 1056

// ---------------- device scratch (zero-initialized .bss; every launch restores zeros) ----------------
__device__ __align__(128) __half d_projS[(size_t)MAXN * 16];
__device__ __align__(128) __half d_projD[(size_t)MAXN * 16];
__device__ __align__(128) __half d_ecA[(size_t)MAXE * 16];    // AoS: 32B per edge, relu'd e_new
__device__ __align__(128) __half2 d_aggE2[(size_t)MAXN * 8];  // fp16 scatter target (self-zeroing)
__device__ __align__(128) float d_xc[(size_t)MAXN * 16];
__device__ __align__(128) float d_counts[MAXN];               // self-zeroing
__device__ __align__(128) float d_small[SMALLN];              // NAGG/EAGG self-zeroing
__device__ int d_nodeDone;                                    // last-block counter (self-resetting)
// PWL tables: 6 global tables, each [j=0..7][seg=0..16] x {A_lo,A_hi,B_lo,B_hi}
__device__ __align__(128) float d_pwlAB[8 * 136 * 4];
__device__ __align__(128) float d_thr[2][16];   // 0 = E-encoder thresholds, 1 = X

// ---------------- helpers ----------------
__device__ __forceinline__ u64 pack2(float lo, float hi) {
    u64 r; asm("mov.b64 %0,{%1,%2};" : "=l"(r) : "f"(lo), "f"(hi)); return r;
}
__device__ __forceinline__ void unpack2(u64 v, float& lo, float& hi) {
    asm("mov.b64 {%0,%1},%2;" : "=f"(lo), "=f"(hi) : "l"(v));
}
__device__ __forceinline__ u64 fma2(u64 a, u64 b, u64 c) {
    u64 r; asm("fma.rn.f32x2 %0,%1,%2,%3;" : "=l"(r) : "l"(a), "l"(b), "l"(c)); return r;
}
__device__ __forceinline__ u64 add2(u64 a, u64 b) {
    u64 r; asm("add.rn.f32x2 %0,%1,%2;" : "=l"(r) : "l"(a), "l"(b)); return r;
}
__device__ __forceinline__ u64 h2f2(u32 u) {
    __half2 h = *reinterpret_cast<__half2*>(&u);
    float2 f = __half22float2(h);
    return pack2(f.x, f.y);
}
__device__ __forceinline__ u32 f2h2u(float a, float b) {
    __half2 h = __floats2half2_rn(a, b);
    return *reinterpret_cast<u32*>(&h);
}
__device__ __forceinline__ u32 hadd2u(u32 a, u32 b) {
    __half2 r = __hadd2(*reinterpret_cast<__half2*>(&a), *reinterpret_cast<__half2*>(&b));
    return *reinterpret_cast<u32*>(&r);
}

// Blackwell 256-bit global load/store
__device__ __forceinline__ void ldg256(const void* p, u32* r) {
    asm("ld.global.v8.b32 {%0,%1,%2,%3,%4,%5,%6,%7}, [%8];"
        : "=r"(r[0]), "=r"(r[1]), "=r"(r[2]), "=r"(r[3]),
          "=r"(r[4]), "=r"(r[5]), "=r"(r[6]), "=r"(r[7])
        : "l"(p));
}
__device__ __forceinline__ void stg256(void* p, const u32* r) {
    asm volatile("st.global.v8.b32 [%0], {%1,%2,%3,%4,%5,%6,%7,%8};"
                 :: "l"(p), "r"(r[0]), "r"(r[1]), "r"(r[2]), "r"(r[3]),
                    "r"(r[4]), "r"(r[5]), "r"(r[6]), "r"(r[7]) : "memory");
}

// acc2[8] += in[16] @ W2 (W2[k][j] packs columns 2j,2j+1 of row k)
__device__ __forceinline__ void mac16_2(const u64 (*__restrict__ W2)[8],
                                        const float* __restrict__ in,
                                        u64* __restrict__ acc2) {
#pragma unroll
    for (int k = 0; k < 16; k++) {
        u64 v2 = pack2(in[k], in[k]);
#pragma unroll
        for (int j = 0; j < 8; j++) acc2[j] = fma2(v2, W2[k][j], acc2[j]);
    }
}

#define RED4(p, a, b, c, d) \
    asm volatile("red.global.add.v4.f32 [%0], {%1,%2,%3,%4};" \
                 :: "l"(p), "f"(a), "f"(b), "f"(c), "f"(d) : "memory")
#define REDH8(p, a, b, c, d) \
    asm volatile("red.global.add.noftz.v4.f16x2 [%0], {%1,%2,%3,%4};" \
                 :: "l"(p), "r"(a), "r"(b), "r"(c), "r"(d) : "memory")

__device__ __forceinline__ void lane_flush16(int b, const float* v, float* gbase) {
    float* p = gbase + b * 16;
    RED4(p,      v[0],  v[1],  v[2],  v[3]);
    RED4(p + 4,  v[4],  v[5],  v[6],  v[7]);
    RED4(p + 8,  v[8],  v[9],  v[10], v[11]);
    RED4(p + 12, v[12], v[13], v[14], v[15]);
}

__device__ __forceinline__ void lane_flush16_h(int b, const u32* aggH, float* gbase) {
    float v[16];
#pragma unroll
    for (int j = 0; j < 8; j++) {
        float2 f = __half22float2(*reinterpret_cast<const __half2*>(&aggH[j]));
        v[2 * j] = f.x; v[2 * j + 1] = f.y;
    }
    lane_flush16(b, v, gbase);
}

__device__ __forceinline__ void warp_flush16(int curB, float* v, float* gbase) {
    const unsigned full = 0xffffffffu;
    int b0 = __shfl_sync(full, curB, 0);
    bool uni = __all_sync(full, (curB == b0) || (curB < 0));
    if (uni) {
#pragma unroll
        for (int h = 0; h < 16; h++) {
            float s = v[h];
            s += __shfl_xor_sync(full, s, 16);
            s += __shfl_xor_sync(full, s, 8);
            s += __shfl_xor_sync(full, s, 4);
            s += __shfl_xor_sync(full, s, 2);
            s += __shfl_xor_sync(full, s, 1);
            v[h] = s;
        }
        if (((threadIdx.x & 31) == 0) && b0 >= 0) lane_flush16(b0, v, gbase);
    } else if (curB >= 0) {
        lane_flush16(curB, v, gbase);
    }
}

__device__ __forceinline__ void warp_flush16_h(int curB, const u32* aggH, float* gbase) {
    float v[16];
#pragma unroll
    for (int j = 0; j < 8; j++) {
        float2 f = __half22float2(*reinterpret_cast<const __half2*>(&aggH[j]));
        v[2 * j] = f.x; v[2 * j + 1] = f.y;
    }
    warp_flush16(curB, v, gbase);
}

__device__ __forceinline__ int find_seg(float v, const float4* sThr4) {
    int seg = 0;
#pragma unroll
    for (int q = 0; q < 4; q++) {
        float4 T = sThr4[q];
        seg += (v > T.x) + (v > T.y) + (v > T.z) + (v > T.w);
    }
    return seg;
}

__device__ __forceinline__ void load_AB(float4* sdst, int tab, int t, int nthreads) {
    const float4* gsrc = reinterpret_cast<const float4*>(d_pwlAB) + tab * 136;
    for (int k = t; k < 136; k += nthreads) sdst[k] = gsrc[k];
}

// threshold/activity derivation for one encoder unit
__device__ __forceinline__ void enc_thr(float w, float b, float& th, int& actR) {
    const float INF = __int_as_float(0x7f800000);
    if (w > 0.f)      { th = -b / w; actR = 1; }
    else if (w < 0.f) { th = -b / w; actR = 0; }
    else if (b > 0.f) { th =  INF;   actR = 0; }
    else              { th =  INF;   actR = 1; }   // never active
}

// ---------------- fused setup: blocks [0,ngrid) = node proj (local tables), block ngrid = PWL+global ----------------
__global__ void __launch_bounds__(256) setup_all_kernel(
    const float* __restrict__ x, int N,
    const float* __restrict__ We_enc, const float* __restrict__ be_enc,
    const float* __restrict__ Wx_enc, const float* __restrict__ bx_enc,
    const float* __restrict__ We_core, const float* __restrict__ Wx_core,
    const float* __restrict__ g,
    const float* __restrict__ Wg_enc, const float* __restrict__ bg_enc,
    const float* __restrict__ be_core, const float* __restrict__ bx_core, int B) {
    int t = threadIdx.x;
    if (blockIdx.x == gridDim.x - 1) {
        // ---- global encoder setup ----
        __shared__ float sG1[NB];
        if (t < B) {
            float g1 = fmaxf(fmaf(g[t], Wg_enc[0], bg_enc[0]), 0.f);
            sG1[t] = g1;
            d_small[G1O + t] = g1;
            d_small[GCO + t] = g1;
        }
        __syncthreads();
        if (t < B * 16) {
            int b = t >> 4, h = t & 15;
            float g1 = sG1[b];
            d_small[GPE + t] = fmaf(g1, We_core[96 * 16 + h] + We_core[97 * 16 + h], be_core[h]);
            d_small[GPX + t] = fmaf(g1, Wx_core[48 * 16 + h] + Wx_core[49 * 16 + h], bx_core[h]);
        }
        // ---- build PWL tables 0-5 + thresholds ----
        // 0: edge step1 (rows 0-15 + 16-31 of We_core), 1: edge step2 (rows 0-15)
        // 2: node step1 (Wx rows 0-15 + 16-31),         3: node step2 (Wx rows 0-15)
        // 4: x1 -> projS step2 (We rows 32-47),          5: x1 -> projD step2 (We rows 64-79)
        __shared__ float sW[2][16], sB[2][16], sT[2][16];
        __shared__ int sAct[2][16], sRank[2][16];
        if (t < 32) {
            int set = t >> 4, h = t & 15;
            float w = set ? Wx_enc[h] : We_enc[h];
            float b = set ? bx_enc[h] : be_enc[h];
            float th; int actR;
            enc_thr(w, b, th, actR);
            sW[set][h] = w; sB[set][h] = b; sT[set][h] = th; sAct[set][h] = actR;
            d_thr[set][h] = th;
        }
        __syncthreads();
        if (t < 32) {
            int set = t >> 4, h = t & 15;
            float th = sT[set][h];
            int r = 0;
            for (int k = 0; k < 16; k++) {
                float tk = sT[set][k];
                if (tk < th || (tk == th && k < h)) r++;
            }
            sRank[set][h] = r;
        }
        __syncthreads();
        for (int f = t; f < 6 * 136; f += blockDim.x) {
            int tab = f / 136;
            int j   = (f % 136) / 17;
            int seg = f % 17;
            int set = (tab == 0 || tab == 1) ? 0 : 1;   // tables 2-5 use the X encoder
            float a0 = 0.f, a1 = 0.f, b0 = 0.f, b1 = 0.f;
            for (int h = 0; h < 16; h++) {
                int active = sAct[set][h] ? (sRank[set][h] < seg) : (sRank[set][h] >= seg);
                if (!active) continue;
                int c0 = 2 * j, c1 = 2 * j + 1;
                float wc0, wc1;
                switch (tab) {
                    case 0: wc0 = We_core[h*16+c0] + We_core[(16+h)*16+c0];
                            wc1 = We_core[h*16+c1] + We_core[(16+h)*16+c1]; break;
                    case 1: wc0 = We_core[h*16+c0];        wc1 = We_core[h*16+c1];        break;
                    case 2: wc0 = Wx_core[h*16+c0] + Wx_core[(16+h)*16+c0];
                            wc1 = Wx_core[h*16+c1] + Wx_core[(16+h)*16+c1]; break;
                    case 3: wc0 = Wx_core[h*16+c0];        wc1 = Wx_core[h*16+c1];        break;
                    case 4: wc0 = We_core[(32+h)*16+c0];   wc1 = We_core[(32+h)*16+c1];   break;
                    default: wc0 = We_core[(64+h)*16+c0];  wc1 = We_core[(64+h)*16+c1];   break;
                }
                float w = sW[set][h], bb = sB[set][h];
                a0 = fmaf(w, wc0, a0);  a1 = fmaf(w, wc1, a1);
                b0 = fmaf(bb, wc0, b0); b1 = fmaf(bb, wc1, b1);
            }
            float* dst = d_pwlAB + (size_t)f * 4;
            dst[0] = a0; dst[1] = a1; dst[2] = b0; dst[3] = b1;
        }
        return;
    }
    // ---- node-proj blocks: build step-1 S/D tables locally (summed rows; no cross-block dependency) ----
    __shared__ float sT1[16], sW1[16], sB1[16];
    __shared__ int sAct1[16], sRank1[16];
    __shared__ __align__(16) ulonglong2 sABS[136], sABD[136];
    if (t < 16) {
        float w = Wx_enc[t], b = bx_enc[t];
        float th; int actR;
        enc_thr(w, b, th, actR);
        sW1[t] = w; sB1[t] = b; sT1[t] = th; sAct1[t] = actR;
    }
    __syncthreads();
    if (t < 16) {
        float th = sT1[t];
        int r = 0;
        for (int k = 0; k < 16; k++) {
            float tk = sT1[k];
            if (tk < th || (tk == th && k < t)) r++;
        }
        sRank1[t] = r;
    }
    __syncthreads();
    for (int f = t; f < 2 * 136; f += 256) {
        int tb = f / 136;
        int j = (f % 136) / 17, seg = f % 17;
        float a0 = 0.f, a1 = 0.f, b0 = 0.f, b1 = 0.f;
        for (int h = 0; h < 16; h++) {
            int active = sAct1[h] ? (sRank1[h] < seg) : (sRank1[h] >= seg);
            if (!active) continue;
            int c0 = 2 * j, c1 = 2 * j + 1;
            float wc0, wc1;
            if (tb == 0) {
                wc0 = We_core[(32+h)*16+c0] + We_core[(48+h)*16+c0];
                wc1 = We_core[(32+h)*16+c1] + We_core[(48+h)*16+c1];
            } else {
                wc0 = We_core[(64+h)*16+c0] + We_core[(80+h)*16+c0];
                wc1 = We_core[(64+h)*16+c1] + We_core[(80+h)*16+c1];
            }
            a0 = fmaf(sW1[h], wc0, a0);  a1 = fmaf(sW1[h], wc1, a1);
            b0 = fmaf(sB1[h], wc0, b0);  b1 = fmaf(sB1[h], wc1, b1);
        }
        ulonglong2 v; v.x = pack2(a0, a1); v.y = pack2(b0, b1);
        if (tb == 0) sABS[j * 17 + seg] = v; else sABD[j * 17 + seg] = v;
    }
    __syncthreads();
    int n = blockIdx.x * 256 + t;
    if (n >= N) return;
    float xv = x[n];
    int seg = 0;
#pragma unroll
    for (int q = 0; q < 16; q++) seg += (xv > sT1[q]);
    u64 xv2 = pack2(xv, xv);
    u32 hs[8], hd[8];
#pragma unroll
    for (int j = 0; j < 8; j++) {
        ulonglong2 abS = sABS[j * 17 + seg];
        ulonglong2 abD = sABD[j * 17 + seg];
        float a, b;
        unpack2(fma2(xv2, abS.x, abS.y), a, b); hs[j] = f2h2u(a, b);
        unpack2(fma2(xv2, abD.x, abD.y), a, b); hd[j] = f2h2u(a, b);
    }
    stg256(d_projS + (size_t)n * 16, hs);
    stg256(d_projD + (size_t)n * 16, hd);
}

// ---------------- fused edge kernel (fp32 acc, fp16 eAgg, 3 CTAs/SM) ----------------
template <int STEP>
__global__ void __launch_bounds__(256, 3) edge_kernel(
    const float* __restrict__ e,
    const int* __restrict__ src, const int* __restrict__ dst,
    const int* __restrict__ eidx,
    const float* __restrict__ We_core,
    const float* __restrict__ We_dec, const float* __restrict__ be_dec,
    const float* __restrict__ We_out, const float* __restrict__ be_out,
    float* __restrict__ out_e, int E) {
    __shared__ __align__(16) ulonglong2 sAB[136];      // PWL(e1 part)
    __shared__ __align__(16) u64 sWb2[16][8];          // ec weights (step2)
    __shared__ __align__(16) u64 sWdec2[16][8];
    __shared__ __align__(16) u64 sGproj2[NB][8];
    __shared__ u64 sBdec2[8];
    __shared__ float4 sThr4[4];
    __shared__ float sWoutT[2][16], sBout[2];

    int t = threadIdx.x;
    load_AB(reinterpret_cast<float4*>(sAB), (STEP == 1) ? 0 : 1, t, 256);
    if (t < 128) {
        int k = t >> 3, j = t & 7;
        if (STEP == 2)
            sWb2[k][j] = pack2(We_core[(16 + k) * 16 + 2 * j], We_core[(16 + k) * 16 + 2 * j + 1]);
        sWdec2[k][j] = pack2(We_dec[k * 16 + 2 * j], We_dec[k * 16 + 2 * j + 1]);
        sGproj2[k][j] = pack2(d_small[GPE + k * 16 + 2 * j], d_small[GPE + k * 16 + 2 * j + 1]);
    }
    if (t < 16) { sWoutT[0][t] = We_out[2 * t]; sWoutT[1][t] = We_out[2 * t + 1]; }
    if (t < 8) sBdec2[t] = pack2(be_dec[2 * t], be_dec[2 * t + 1]);
    if (t < 4) sThr4[t] = reinterpret_cast<const float4*>(d_thr[0])[t];
    if (t < 2) sBout[t] = be_out[t];
    __syncthreads();

    u32 eAggH[8];
#pragma unroll
    for (int j = 0; j < 8; j++) eAggH[j] = 0u;
    int curB = -1;

    int base = blockIdx.x * (256 * EPT);
#pragma unroll
    for (int it = 0; it < EPT; ++it) {
        int i = base + it * 256 + t;
        if (i < E) {
            float ev = e[i];
            int s = src[i], d = dst[i], b = eidx[i];

            u32 sw[8], dw[8];
            ldg256(d_projS + (size_t)s * 16, sw);
            ldg256(d_projD + (size_t)d * 16, dw);

            int seg = find_seg(ev, sThr4);
            u64 ev2 = pack2(ev, ev);

            u64 acc2[8];
#pragma unroll
            for (int j = 0; j < 8; j++) {
                ulonglong2 ab = sAB[j * 17 + seg];
                acc2[j] = add2(add2(h2f2(sw[j]), h2f2(dw[j])),
                               add2(sGproj2[b][j], fma2(ev2, ab.x, ab.y)));
            }
            if (STEP == 2) {
                u32 ec[8];
                ldg256(d_ecA + (size_t)i * 16, ec);
#pragma unroll
                for (int kk = 0; kk < 8; kk++) {
                    float lo, hi; unpack2(h2f2(ec[kk]), lo, hi);
                    u64 l2 = pack2(lo, lo), h2v = pack2(hi, hi);
#pragma unroll
                    for (int j = 0; j < 8; j++) acc2[j] = fma2(l2, sWb2[2 * kk][j], acc2[j]);
#pragma unroll
                    for (int j = 0; j < 8; j++) acc2[j] = fma2(h2v, sWb2[2 * kk + 1][j], acc2[j]);
                }
            }
            float acc[16];
            u32 hh[8];
#pragma unroll
            for (int j = 0; j < 8; j++) {
                float lo, hi; unpack2(acc2[j], lo, hi);
                lo = fmaxf(lo, 0.f); hi = fmaxf(hi, 0.f);
                acc[2 * j] = lo; acc[2 * j + 1] = hi;
                hh[j] = f2h2u(lo, hi);
            }

            if (STEP == 1) {
                stg256(d_ecA + (size_t)i * 16, hh);
                asm volatile("red.global.add.f32 [%0], %1;"
                             :: "l"(d_counts + d), "f"(1.0f) : "memory");
            }
            {
                __half2* p = d_aggE2 + (size_t)d * 8;
                REDH8(p, hh[0], hh[1], hh[2], hh[3]);
                REDH8(p + 4, hh[4], hh[5], hh[6], hh[7]);
            }
            if (b != curB) {
                if (curB >= 0) lane_flush16_h(curB, eAggH, d_small + EAGG);
                curB = b;
#pragma unroll
                for (int j = 0; j < 8; j++) eAggH[j] = 0u;
            }
#pragma unroll
            for (int j = 0; j < 8; j++) eAggH[j] = hadd2u(eAggH[j], hh[j]);

            u64 dacc[8];
#pragma unroll
            for (int j = 0; j < 8; j++) dacc[j] = sBdec2[j];
            mac16_2(sWdec2, acc, dacc);
            float o0 = sBout[0], o1 = sBout[1];
#pragma unroll
            for (int j = 0; j < 8; j++) {
                float lo, hi; unpack2(dacc[j], lo, hi);
                float r0 = fmaxf(lo, 0.f), r1 = fmaxf(hi, 0.f);
                o0 = fmaf(r0, sWoutT[0][2 * j], fmaf(r1, sWoutT[0][2 * j + 1], o0));
                o1 = fmaf(r0, sWoutT[1][2 * j], fmaf(r1, sWoutT[1][2 * j + 1], o1));
            }
            reinterpret_cast<float2*>(out_e)[(size_t)(STEP - 1) * E + i] = make_float2(o0, o1);
        }
    }
    warp_flush16_h(curB, eAggH, d_small + EAGG);
}

// ---------------- node kernel + fused global epilogue (last CTA) ----------------
template <int STEP>
__global__ void __launch_bounds__(256) node_kernel(
    const float* __restrict__ x, const int* __restrict__ nidx,
    const float* __restrict__ Wx_core,
    const float* __restrict__ We_core,
    const float* __restrict__ Wx_dec, const float* __restrict__ bx_dec,
    const float* __restrict__ Wx_out, const float* __restrict__ bx_out,
    float* __restrict__ out_x,
    const float* __restrict__ Wg_core, const float* __restrict__ bg_core,
    const float* __restrict__ Wg_dec, const float* __restrict__ bg_dec,
    const float* __restrict__ Wg_out, const float* __restrict__ bg_out,
    const float* __restrict__ be_core, const float* __restrict__ bx_core,
    float* __restrict__ out_g, int N, int B) {
    __shared__ __align__(16) ulonglong2 sABX[136];
    __shared__ __align__(16) ulonglong2 sABS[136], sABD[136]; // step1 only (tables 4,5)
    __shared__ __align__(16) u64 sWxB2[16][8];                // step2 only
    __shared__ __align__(16) u64 sWagg2[16][8], sWdec2[16][8];
    __shared__ __align__(16) u64 sWSb2[16][8], sWDb2[16][8];  // step1 only
    __shared__ __align__(16) u64 sGprojX2[NB][8];
    __shared__ u64 sBdec2[8];
    __shared__ float4 sThr4[4];
    __shared__ float sWoutT[2][16], sBout[2];
    __shared__ int sIsLast;

    int t = threadIdx.x;
    load_AB(reinterpret_cast<float4*>(sABX), (STEP == 1) ? 2 : 3, t, 256);
    if (STEP == 1) {
        load_AB(reinterpret_cast<float4*>(sABS), 4, t, 256);
        load_AB(reinterpret_cast<float4*>(sABD), 5, t, 256);
    }
    if (t < 128) {
        int k = t >> 3, j = t & 7;
        int c0 = 2 * j, c1 = 2 * j + 1;
        if (STEP == 1) {
            sWSb2[k][j] = pack2(We_core[(48 + k) * 16 + c0], We_core[(48 + k) * 16 + c1]);
            sWDb2[k][j] = pack2(We_core[(80 + k) * 16 + c0], We_core[(80 + k) * 16 + c1]);
        } else {
            sWxB2[k][j] = pack2(Wx_core[(16 + k) * 16 + c0], Wx_core[(16 + k) * 16 + c1]);
        }
        sWagg2[k][j] = pack2(Wx_core[(32 + k) * 16 + c0], Wx_core[(32 + k) * 16 + c1]);
        sWdec2[k][j] = pack2(Wx_dec[k * 16 + c0], Wx_dec[k * 16 + c1]);
        sGprojX2[k][j] = pack2(d_small[GPX + k * 16 + c0], d_small[GPX + k * 16 + c1]);
    }
    if (t < 16) { sWoutT[0][t] = Wx_out[2 * t]; sWoutT[1][t] = Wx_out[2 * t + 1]; }
    if (t < 8) sBdec2[t] = pack2(bx_dec[2 * t], bx_dec[2 * t + 1]);
    if (t < 4) sThr4[t] = reinterpret_cast<const float4*>(d_thr[1])[t];
    if (t < 2) sBout[t] = bx_out[t];
    __syncthreads();

    int n = blockIdx.x * 256 + t;
    float xnew[16];
#pragma unroll
    for (int hh = 0; hh < 16; hh++) xnew[hh] = 0.f;
    int b = -1;

    if (n < N) {
        b = nidx[n];
        float xv = x[n];
        int seg = find_seg(xv, sThr4);
        u64 xv2 = pack2(xv, xv);
        u64 acc2[8];
#pragma unroll
        for (int j = 0; j < 8; j++) {
            ulonglong2 ab = sABX[j * 17 + seg];
            acc2[j] = add2(sGprojX2[b][j], fma2(xv2, ab.x, ab.y));
        }
        if (STEP == 2) {
            float xc[16];
            u32 xr[8];
            ldg256(d_xc + (size_t)n * 16, xr);
#pragma unroll
            for (int q = 0; q < 8; q++) xc[q] = __uint_as_float(xr[q]);
            ldg256(d_xc + (size_t)n * 16 + 8, xr);
#pragma unroll
            for (int q = 0; q < 8; q++) xc[8 + q] = __uint_as_float(xr[q]);
            mac16_2(sWxB2, xc, acc2);
        }
        float cnt = d_counts[n];
        float inv = 1.0f / fmaxf(cnt, 1.0f);
        float am[16];
        {
            u32 w[8];
            ldg256(d_aggE2 + (size_t)n * 8, w);
#pragma unroll
            for (int q = 0; q < 8; q++) {
                float2 f = __half22float2(*reinterpret_cast<__half2*>(&w[q]));
                am[2 * q] = f.x * inv; am[2 * q + 1] = f.y * inv;
            }
        }
        {
            u32 z[8] = {0, 0, 0, 0, 0, 0, 0, 0};
            stg256(d_aggE2 + (size_t)n * 8, z);
            if (STEP == 2) d_counts[n] = 0.f;
        }
        mac16_2(sWagg2, am, acc2);
#pragma unroll
        for (int j = 0; j < 8; j++) unpack2(acc2[j], xnew[2 * j], xnew[2 * j + 1]);
#pragma unroll
        for (int hh = 0; hh < 16; hh++) xnew[hh] = fmaxf(xnew[hh], 0.f);

        if (STEP == 1) {
            stg256(d_xc + (size_t)n * 16, reinterpret_cast<const u32*>(xnew));
            stg256(d_xc + (size_t)n * 16 + 8, reinterpret_cast<const u32*>(xnew) + 8);
            u64 psv2[8], pdv2[8];
#pragma unroll
            for (int j = 0; j < 8; j++) {
                ulonglong2 abS = sABS[j * 17 + seg];
                ulonglong2 abD = sABD[j * 17 + seg];
                psv2[j] = fma2(xv2, abS.x, abS.y);
                pdv2[j] = fma2(xv2, abD.x, abD.y);
            }
            mac16_2(sWSb2, xnew, psv2);
            mac16_2(sWDb2, xnew, pdv2);
            u32 hs[8], hd[8];
#pragma unroll
            for (int j = 0; j < 8; j++) {
                float a, c;
                unpack2(psv2[j], a, c); hs[j] = f2h2u(a, c);
                unpack2(pdv2[j], a, c); hd[j] = f2h2u(a, c);
            }
            stg256(d_projS + (size_t)n * 16, hs);
            stg256(d_projD + (size_t)n * 16, hd);
        }
        u64 xd2[8];
#pragma unroll
        for (int j = 0; j < 8; j++) xd2[j] = sBdec2[j];
        mac16_2(sWdec2, xnew, xd2);
        float o0 = sBout[0], o1 = sBout[1];
#pragma unroll
        for (int j = 0; j < 8; j++) {
            float lo, hi; unpack2(xd2[j], lo, hi);
            float r0 = fmaxf(lo, 0.f), r1 = fmaxf(hi, 0.f);
            o0 = fmaf(r0, sWoutT[0][2 * j], fmaf(r1, sWoutT[0][2 * j + 1], o0));
            o1 = fmaf(r0, sWoutT[1][2 * j], fmaf(r1, sWoutT[1][2 * j + 1], o1));
        }
        reinterpret_cast<float2*>(out_x)[(size_t)(STEP - 1) * N + n] = make_float2(o0, o1);
    }
    warp_flush16(b, xnew, d_small + NAGG);

    // ---- last-CTA global epilogue ----
    __threadfence();
    if (t == 0)
        sIsLast = (atomicAdd(&d_nodeDone, 1) == (int)gridDim.x - 1);
    __syncthreads();
    if (sIsLast) {
        __threadfence();
        if (t == 0) d_nodeDone = 0;
        if (t < B) {
            float g1 = d_small[G1O + t], gc = d_small[GCO + t];
            float acc = bg_core[0] + g1 * Wg_core[0] + gc * Wg_core[1];
#pragma unroll
            for (int h = 0; h < 16; h++) acc = fmaf(d_small[NAGG + t * 16 + h], Wg_core[2 + h], acc);
#pragma unroll
            for (int h = 0; h < 16; h++) acc = fmaf(d_small[EAGG + t * 16 + h], Wg_core[18 + h], acc);
            float gn = fmaxf(acc, 0.f);
            d_small[GCO + t] = gn;
            float gd = fmaxf(fmaf(gn, Wg_dec[0], bg_dec[0]), 0.f);
            out_g[(STEP - 1) * B + t] = fmaf(gd, Wg_out[0], bg_out[0]);
        }
        __syncthreads();
        d_small[NAGG + t] = 0.f;
        d_small[EAGG + t] = 0.f;
        if (STEP == 1 && t < B * 16) {
            int bb = t >> 4, h = t & 15;
            float g1 = d_small[G1O + bb], gn = d_small[GCO + bb];
            d_small[GPE + t] = fmaf(g1, We_core[96 * 16 + h], fmaf(gn, We_core[97 * 16 + h], be_core[h]));
            d_small[GPX + t] = fmaf(g1, Wx_core[48 * 16 + h], fmaf(gn, Wx_core[49 * 16 + h], bx_core[h]));
        }
    }
}

// ---------------- launch (5 graph nodes) ----------------
extern "C" void kernel_launch(void* const* d_in, const int* in_sizes, int n_in,
                              void* d_out, int out_size) {
    const float* x       = (const float*)d_in[0];
    const float* e       = (const float*)d_in[1];
    const float* g       = (const float*)d_in[2];
    const float* We_enc  = (const float*)d_in[3];
    const float* be_enc  = (const float*)d_in[4];
    const float* Wx_enc  = (const float*)d_in[5];
    const float* bx_enc  = (const float*)d_in[6];
    const float* Wg_enc  = (const float*)d_in[7];
    const float* bg_enc  = (const float*)d_in[8];
    const float* We_core = (const float*)d_in[9];
    const float* be_core = (const float*)d_in[10];
    const float* Wx_core = (const float*)d_in[11];
    const float* bx_core = (const float*)d_in[12];
    const float* Wg_core = (const float*)d_in[13];
    const float* bg_core = (const float*)d_in[14];
    const float* We_dec  = (const float*)d_in[15];
    const float* be_dec  = (const float*)d_in[16];
    const float* Wx_dec  = (const float*)d_in[17];
    const float* bx_dec  = (const float*)d_in[18];
    const float* Wg_dec  = (const float*)d_in[19];
    const float* bg_dec  = (const float*)d_in[20];
    const float* We_out  = (const float*)d_in[21];
    const float* be_out  = (const float*)d_in[22];
    const float* Wx_out  = (const float*)d_in[23];
    const float* bx_out  = (const float*)d_in[24];
    const float* Wg_out  = (const float*)d_in[25];
    const float* bg_out  = (const float*)d_in[26];
    const int*   edges   = (const int*)d_in[27];
    const int*   nidx    = (const int*)d_in[28];
    const int*   eidx    = (const int*)d_in[29];

    int N = in_sizes[0];
    int E = in_sizes[1];
    int B = in_sizes[2];
    float* out = (float*)d_out;
    float* out_e = out;
    float* out_x = out + (size_t)4 * E;
    float* out_g = out + (size_t)4 * E + (size_t)4 * N;

    const int* src = edges;
    const int* dst = edges + E;

    int egrid = (E + 256 * EPT - 1) / (256 * EPT);
    int ngrid = (N + 255) / 256;

    setup_all_kernel<<<ngrid + 1, 256>>>(x, N, We_enc, be_enc, Wx_enc, bx_enc,
                                         We_core, Wx_core, g, Wg_enc, bg_enc,
                                         be_core, bx_core, B);

    // ---- step 1 ----
    edge_kernel<1><<<egrid, 256>>>(e, src, dst, eidx, We_core,
                                   We_dec, be_dec, We_out, be_out, out_e, E);
    node_kernel<1><<<ngrid, 256>>>(x, nidx, Wx_core, We_core,
                                   Wx_dec, bx_dec, Wx_out, bx_out, out_x,
                                   Wg_core, bg_core, Wg_dec, bg_dec, Wg_out, bg_out,
                                   be_core, bx_core, out_g, N, B);

    // ---- step 2 ----
    edge_kernel<2><<<egrid, 256>>>(e, src, dst, eidx, We_core,
                                   We_dec, be_dec, We_out, be_out, out_e, E);
    node_kernel<2><<<ngrid, 256>>>(x, nidx, Wx_core, We_core,
                                   Wx_dec, bx_dec, Wx_out, bx_out, out_x,
                                   Wg_core, bg_core, Wg_dec, bg_dec, Wg_out, bg_out,
                                   be_core, bx_core, out_g, N, B);
}